// round 14
// baseline (speedup 1.0000x reference)
#include <cuda_runtime.h>
#include <cuda_bf16.h>
#include <math_constants.h>
#include <mma.h>

using namespace nvcuda;

// Problem constants
#define NB   4
#define SL   2048
#define EMB  512
#define NH   8
#define DH   64
#define WIN  128

// ---------------------------------------------------------------------------
// Device scratch (no allocations allowed)
// ---------------------------------------------------------------------------
static __device__ __nv_bfloat16 g_Qh[NB * NH * SL * DH];  // [b,h,s,d] hi/lo
static __device__ __nv_bfloat16 g_Ql[NB * NH * SL * DH];
static __device__ __nv_bfloat16 g_Kh[NB * NH * SL * DH];
static __device__ __nv_bfloat16 g_Kl[NB * NH * SL * DH];
static __device__ __nv_bfloat16 g_Vh[NB * NH * SL * DH];
static __device__ __nv_bfloat16 g_Vl[NB * NH * SL * DH];

static __device__ __nv_bfloat16 g_Xh[NB * SL * EMB];      // embeddings hi/lo
static __device__ __nv_bfloat16 g_Xl[NB * SL * EMB];
static __device__ __nv_bfloat16 g_Winh[3 * EMB * EMB];    // in_proj_w hi/lo
static __device__ __nv_bfloat16 g_Winl[3 * EMB * EMB];
static __device__ __nv_bfloat16 g_Wouth[EMB * EMB];       // out_w hi/lo
static __device__ __nv_bfloat16 g_Woutl[EMB * EMB];
static __device__ __nv_bfloat16 g_ctxh[NB * SL * EMB];    // ctx hi/lo
static __device__ __nv_bfloat16 g_ctxl[NB * SL * EMB];

// ---------------------------------------------------------------------------
// cp.async helpers
// ---------------------------------------------------------------------------
__device__ __forceinline__ unsigned smem_u32(const void* p) {
    unsigned a;
    asm("{ .reg .u64 t; cvta.to.shared.u64 t, %1; cvt.u32.u64 %0, t; }"
        : "=r"(a) : "l"(p));
    return a;
}
#define CP_ASYNC16(dst_u32, src_ptr) \
    asm volatile("cp.async.cg.shared.global [%0], [%1], 16;" \
        :: "r"(dst_u32), "l"(src_ptr))
#define CP_COMMIT() asm volatile("cp.async.commit_group;" ::: "memory")
#define CP_WAIT1()  asm volatile("cp.async.wait_group 1;" ::: "memory")
#define CP_WAIT0()  asm volatile("cp.async.wait_group 0;" ::: "memory")

// ---------------------------------------------------------------------------
// float atomic max (target pre-initialized to -inf)
// ---------------------------------------------------------------------------
__device__ __forceinline__ void atomicMaxF(float* addr, float v) {
    if (v >= 0.0f) atomicMax((int*)addr, __float_as_int(v));
    else           atomicMin((unsigned int*)addr, __float_as_uint(v));
}

__global__ void pooled_init_kernel(float* p) {
    int i = blockIdx.x * 256 + threadIdx.x;
    if (i < NB * EMB) p[i] = -CUDART_INF_F;
}

// ---------------------------------------------------------------------------
// Prep: split all three fp32 tensors into bf16 hi/lo pairs, one launch.
// ---------------------------------------------------------------------------
#define N4_X (NB * SL * EMB / 4)       // 1048576
#define N4_W (3 * EMB * EMB / 4)       // 196608
#define N4_O (EMB * EMB / 4)           // 65536
#define N4_ALL (N4_X + N4_W + N4_O)

__global__ __launch_bounds__(256)
void split_all_kernel(const float* __restrict__ x,
                      const float* __restrict__ winw,
                      const float* __restrict__ outw)
{
    int i = blockIdx.x * 256 + threadIdx.x;
    if (i >= N4_ALL) return;
    const float* src;
    __nv_bfloat16 *hi, *lo;
    int idx;
    if (i < N4_X)            { src = x;    hi = g_Xh;    lo = g_Xl;    idx = i; }
    else if (i < N4_X + N4_W){ src = winw; hi = g_Winh;  lo = g_Winl;  idx = i - N4_X; }
    else                     { src = outw; hi = g_Wouth; lo = g_Woutl; idx = i - N4_X - N4_W; }

    float4 v = ((const float4*)src)[idx];
    __nv_bfloat162 h01 = __floats2bfloat162_rn(v.x, v.y);
    __nv_bfloat162 h23 = __floats2bfloat162_rn(v.z, v.w);
    float2 f01 = __bfloat1622float2(h01);
    float2 f23 = __bfloat1622float2(h23);
    __nv_bfloat162 l01 = __floats2bfloat162_rn(v.x - f01.x, v.y - f01.y);
    __nv_bfloat162 l23 = __floats2bfloat162_rn(v.z - f23.x, v.w - f23.y);
    uint2 hv, lv;
    hv.x = *(unsigned*)&h01; hv.y = *(unsigned*)&h23;
    lv.x = *(unsigned*)&l01; lv.y = *(unsigned*)&l23;
    ((uint2*)hi)[idx] = hv;
    ((uint2*)lo)[idx] = lv;
}

// ---------------------------------------------------------------------------
// Split-bf16 WMMA GEMM core, cp.async double-buffered, 128x256 CTA tile.
// 8 warps, each computes 64x64 (warp grid 2 M-halves x 4 N-quarters).
//   C[128x256] = A[m0..+128, 0..512] . B[n0..+256, 0..512]^T
// K-chunk 32, LDM 40 (80 B rows: 16B-aligned cp.async, conflict-free).
// stage = Ah+Al (2x10240) + Bh+Bl (2x20480) = 61440 B; 2 stages = 122880 B.
// Epilogue: two 128-col passes through float sC[128][132].
// ---------------------------------------------------------------------------
#define KC     32
#define LDM    40
#define ATILEB (128 * LDM * 2)             // 10240
#define BTILEB (256 * LDM * 2)             // 20480
#define STAGEB (2 * ATILEB + 2 * BTILEB)   // 61440
#define SC_LD  132
#define GEMM_SMEM_BYTES (2 * STAGEB)       // 122880

// Runs mainloop leaving accumulators in acc[4][4]; caller does the epilogue.
__device__ __forceinline__ void gemm_wmma_mainloop(
    const __nv_bfloat16* __restrict__ Ah, const __nv_bfloat16* __restrict__ Al,
    const __nv_bfloat16* __restrict__ Bh, const __nv_bfloat16* __restrict__ Bl,
    char* smem, int m0, int n0,
    wmma::fragment<wmma::accumulator, 16, 16, 16, float> (&acc)[4][4])
{
    const int tid = threadIdx.x;
    const int wid = tid >> 5;
    const int wm  = wid & 1;               // M half (64 rows)
    const int wn  = wid >> 1;              // N quarter (64 cols)

    #pragma unroll
    for (int i = 0; i < 4; i++)
        #pragma unroll
        for (int j = 0; j < 4; j++) wmma::fill_fragment(acc[i][j], 0.0f);

    const int rowA = tid >> 1;             // 0..127
    const int kgA  = (tid & 1) * 16;       // 0 / 16
    const __nv_bfloat16* pAh = Ah + (size_t)(m0 + rowA) * EMB + kgA;
    const __nv_bfloat16* pAl = Al + (size_t)(m0 + rowA) * EMB + kgA;
    const __nv_bfloat16* pBh = Bh + (size_t)(n0 + tid) * EMB;   // row = tid
    const __nv_bfloat16* pBl = Bl + (size_t)(n0 + tid) * EMB;

    const unsigned sbase = smem_u32(smem);
    const unsigned dA = (unsigned)((rowA * LDM + kgA) * 2);     // 16B-aligned
    const unsigned dB = (unsigned)(tid * LDM * 2);              // 80B rows

    auto issue = [&](int ch, int buf) {
        const int k0 = ch * KC;
        unsigned st = sbase + (unsigned)buf * STAGEB;
        #pragma unroll
        for (int u = 0; u < 2; u++) {      // A: 16 cols = 2 x 16B
            CP_ASYNC16(st + 0u * ATILEB + dA + u * 16, pAh + k0 + u * 8);
            CP_ASYNC16(st + 1u * ATILEB + dA + u * 16, pAl + k0 + u * 8);
        }
        #pragma unroll
        for (int u = 0; u < 4; u++) {      // B: 32 cols = 4 x 16B
            CP_ASYNC16(st + 2u * ATILEB + dB + u * 16,          pBh + k0 + u * 8);
            CP_ASYNC16(st + 2u * ATILEB + BTILEB + dB + u * 16, pBl + k0 + u * 8);
        }
        CP_COMMIT();
    };

    issue(0, 0);
    issue(1, 1);

    const int NCH = EMB / KC;              // 16
    for (int ch = 0; ch < NCH; ch++) {
        if (ch < NCH - 1) CP_WAIT1(); else CP_WAIT0();
        __syncthreads();

        const char* stage = smem + (size_t)(ch & 1) * STAGEB;
        const __nv_bfloat16* sAhi = (const __nv_bfloat16*)(stage);
        const __nv_bfloat16* sAlo = (const __nv_bfloat16*)(stage + ATILEB);
        const __nv_bfloat16* sBhi = (const __nv_bfloat16*)(stage + 2 * ATILEB);
        const __nv_bfloat16* sBlo = (const __nv_bfloat16*)(stage + 2 * ATILEB + BTILEB);

        #pragma unroll
        for (int ks = 0; ks < KC / 16; ks++) {
            const int kb = ks * 16;
            wmma::fragment<wmma::matrix_a, 16, 16, 16, __nv_bfloat16,
                           wmma::row_major> ahi[4], alo[4];
            #pragma unroll
            for (int mt = 0; mt < 4; mt++) {
                int r = (wm * 64 + mt * 16) * LDM + kb;
                wmma::load_matrix_sync(ahi[mt], sAhi + r, LDM);
                wmma::load_matrix_sync(alo[mt], sAlo + r, LDM);
            }
            #pragma unroll
            for (int nt = 0; nt < 4; nt++) {
                wmma::fragment<wmma::matrix_b, 16, 16, 16, __nv_bfloat16,
                               wmma::col_major> bhi, blo;
                int r = (wn * 64 + nt * 16) * LDM + kb;
                wmma::load_matrix_sync(bhi, sBhi + r, LDM);
                wmma::load_matrix_sync(blo, sBlo + r, LDM);
                #pragma unroll
                for (int mt = 0; mt < 4; mt++) {
                    wmma::mma_sync(acc[mt][nt], ahi[mt], bhi, acc[mt][nt]);
                    wmma::mma_sync(acc[mt][nt], ahi[mt], blo, acc[mt][nt]);
                    wmma::mma_sync(acc[mt][nt], alo[mt], bhi, acc[mt][nt]);
                }
            }
        }
        __syncthreads();
        if (ch + 2 < NCH) issue(ch + 2, ch & 1);
    }
}

// Store pass p (N-cols p*128..p*128+127) of acc into sC. Caller barriers.
__device__ __forceinline__ void gemm_store_pass(
    wmma::fragment<wmma::accumulator, 16, 16, 16, float> (&acc)[4][4],
    float* sC, int p)
{
    const int wid = threadIdx.x >> 5;
    const int wm  = wid & 1;
    const int wn  = wid >> 1;
    if ((wn >> 1) == p) {
        #pragma unroll
        for (int mt = 0; mt < 4; mt++)
            #pragma unroll
            for (int nt = 0; nt < 4; nt++)
                wmma::store_matrix_sync(
                    sC + (size_t)(wm * 64 + mt * 16) * SC_LD
                       + (wn & 1) * 64 + nt * 16,
                    acc[mt][nt], SC_LD, wmma::mem_row_major);
    }
}

// ---------------------------------------------------------------------------
// Kernel 1: QKV projection, 128x256 tiles. Epilogue adds bias and scatters
// bf16 hi/lo into g_Q/g_K/g_V, one 128-col pass at a time.
// ---------------------------------------------------------------------------
__global__ __launch_bounds__(256, 1)
void qkv_tc_kernel(const float* __restrict__ bias)
{
    extern __shared__ __align__(16) char smem[];
    const int m0 = blockIdx.y * 128, n0 = blockIdx.x * 256;

    wmma::fragment<wmma::accumulator, 16, 16, 16, float> acc[4][4];
    gemm_wmma_mainloop(g_Xh, g_Xl, g_Winh, g_Winl, smem, m0, n0, acc);

    float* sC = (float*)smem;
    const int tid  = threadIdx.x;
    const int row  = tid >> 1;
    const int koff = (tid & 1) * 32;
    const int m    = m0 + row;
    const int bb   = m >> 11;
    const int s    = m & (SL - 1);

    for (int p = 0; p < 2; p++) {
        gemm_store_pass(acc, sC, p);
        __syncthreads();
        #pragma unroll
        for (int ph = 0; ph < 2; ph++) {
            const int nb  = n0 + p * 128 + ph * 64;
            const int sel = nb >> 9;          // 0=Q 1=K 2=V
            const int hh  = (nb >> 6) & 7;
            __nv_bfloat16* dh = (sel == 0) ? g_Qh : (sel == 1) ? g_Kh : g_Vh;
            __nv_bfloat16* dl = (sel == 0) ? g_Ql : (sel == 1) ? g_Kl : g_Vl;
            size_t base = (((size_t)(bb * NH + hh) * SL + s) << 6);
            #pragma unroll
            for (int f = 0; f < 8; f++) {
                int c = koff + f * 4;
                float4 v;
                v.x = sC[(size_t)row * SC_LD + ph * 64 + c + 0] + bias[nb + c + 0];
                v.y = sC[(size_t)row * SC_LD + ph * 64 + c + 1] + bias[nb + c + 1];
                v.z = sC[(size_t)row * SC_LD + ph * 64 + c + 2] + bias[nb + c + 2];
                v.w = sC[(size_t)row * SC_LD + ph * 64 + c + 3] + bias[nb + c + 3];
                __nv_bfloat162 h01 = __floats2bfloat162_rn(v.x, v.y);
                __nv_bfloat162 h23 = __floats2bfloat162_rn(v.z, v.w);
                float2 f01 = __bfloat1622float2(h01);
                float2 f23 = __bfloat1622float2(h23);
                __nv_bfloat162 l01 = __floats2bfloat162_rn(v.x - f01.x, v.y - f01.y);
                __nv_bfloat162 l23 = __floats2bfloat162_rn(v.z - f23.x, v.w - f23.y);
                uint2 hv, lv;
                hv.x = *(unsigned*)&h01; hv.y = *(unsigned*)&h23;
                lv.x = *(unsigned*)&l01; lv.y = *(unsigned*)&l23;
                *(uint2*)(dh + base + c) = hv;
                *(uint2*)(dl + base + c) = lv;
            }
        }
        __syncthreads();
    }
}

// ---------------------------------------------------------------------------
// Kernel 2: banded attention — unchanged from R13 (passing, 477 µs config).
// ---------------------------------------------------------------------------
#define AT_SMEM_BYTES (9216 + 36864 + 50176)

__global__ __launch_bounds__(256, 2)
void attn_kernel(float* __restrict__ wout)
{
    extern __shared__ __align__(16) char smem[];
    __nv_bfloat16* sQh = (__nv_bfloat16*)smem;            // 32*72
    __nv_bfloat16* sQl = sQh + 32 * 72;
    __nv_bfloat16* sKh = (__nv_bfloat16*)(smem + 9216);   // 128*72
    __nv_bfloat16* sKl = sKh + 128 * 72;
    float*         sS  = (float*)(smem + 9216 + 36864);   // 32*392
    __nv_bfloat16* sP  = (__nv_bfloat16*)sS;  // row q: hi at q*784+o, lo +392
    float*         sCtx = (float*)smem;                   // 32*68 (reuse sQ)

    const int tid  = threadIdx.x;
    const int lane = tid & 31;
    const int warp = tid >> 5;
    const int b    = blockIdx.y;
    const int i0   = blockIdx.x * 32;
    const int j0   = i0 - WIN;

    float wsum[36];
    #pragma unroll
    for (int i = 0; i < 36; i++) wsum[i] = 0.0f;

    const int qrow = tid >> 3, qdp = (tid & 7) * 8;       // Q loads
    const int krow = tid >> 1, kdp = (tid & 1) * 32;      // K/V loads

    for (int h = 0; h < NH; h++) {
        __syncthreads();    // prev head's sCtx reads & P reads done

        // ---- load Q tile hi/lo ----
        {
            size_t off = ((size_t)(b * NH + h) * SL + i0 + qrow) * DH + qdp;
            *(uint4*)(sQh + qrow * 72 + qdp) = *(const uint4*)(g_Qh + off);
            *(uint4*)(sQl + qrow * 72 + qdp) = *(const uint4*)(g_Ql + off);
        }

        // ---- QK scores: 3 chunks of 128 keys ----
        for (int c = 0; c < 3; c++) {
            int kg = j0 + c * 128 + krow;
            bool ok = ((unsigned)kg < (unsigned)SL);
            size_t off = ((size_t)(b * NH + h) * SL + (ok ? kg : 0)) * DH + kdp;
            const uint4 z = make_uint4(0, 0, 0, 0);
            #pragma unroll
            for (int u = 0; u < 4; u++) {
                *(uint4*)(sKh + krow * 72 + kdp + u * 8) =
                    ok ? *(const uint4*)(g_Kh + off + u * 8) : z;
                *(uint4*)(sKl + krow * 72 + kdp + u * 8) =
                    ok ? *(const uint4*)(g_Kl + off + u * 8) : z;
            }
            __syncthreads();

            wmma::fragment<wmma::accumulator, 16, 16, 16, float> acc[2];
            wmma::fill_fragment(acc[0], 0.0f);
            wmma::fill_fragment(acc[1], 0.0f);
            #pragma unroll
            for (int kt = 0; kt < 4; kt++) {
                wmma::fragment<wmma::matrix_b, 16, 16, 16, __nv_bfloat16,
                               wmma::col_major> bhi, blo;
                wmma::load_matrix_sync(bhi, sKh + warp * 16 * 72 + kt * 16, 72);
                wmma::load_matrix_sync(blo, sKl + warp * 16 * 72 + kt * 16, 72);
                #pragma unroll
                for (int mt = 0; mt < 2; mt++) {
                    wmma::fragment<wmma::matrix_a, 16, 16, 16, __nv_bfloat16,
                                   wmma::row_major> ahi, alo;
                    wmma::load_matrix_sync(ahi, sQh + mt * 16 * 72 + kt * 16, 72);
                    wmma::load_matrix_sync(alo, sQl + mt * 16 * 72 + kt * 16, 72);
                    wmma::mma_sync(acc[mt], ahi, bhi, acc[mt]);
                    wmma::mma_sync(acc[mt], ahi, blo, acc[mt]);
                    wmma::mma_sync(acc[mt], alo, bhi, acc[mt]);
                }
            }
            #pragma unroll
            for (int mt = 0; mt < 2; mt++)
                wmma::store_matrix_sync(sS + mt * 16 * 392 + c * 128 + warp * 16,
                                        acc[mt], 392, wmma::mem_row_major);
            __syncthreads();
        }

        // ---- prefetch V chunk 0 into the now-dead K tile (no barrier yet) ----
        {
            int kg = j0 + krow;
            bool ok = ((unsigned)kg < (unsigned)SL);
            size_t off = ((size_t)(b * NH + h) * SL + (ok ? kg : 0)) * DH + kdp;
            const uint4 z = make_uint4(0, 0, 0, 0);
            #pragma unroll
            for (int u = 0; u < 4; u++) {
                *(uint4*)(sKh + krow * 72 + kdp + u * 8) =
                    ok ? *(const uint4*)(g_Vh + off + u * 8) : z;
                *(uint4*)(sKl + krow * 72 + kdp + u * 8) =
                    ok ? *(const uint4*)(g_Vl + off + u * 8) : z;
            }
        }

        // ---- softmax + in-place P split (warp owns rows warp*4..+3) ----
        #pragma unroll
        for (int qq = 0; qq < 4; qq++) {
            const int q = warp * 4 + qq;
            const float* Sr = sS + q * 392;
            float lv[9];
            float mx = -1e30f;
            #pragma unroll
            for (int r = 0; r < 9; r++) {
                int o = lane + r * 32;
                int j = j0 + o;
                int dlt = (i0 + q) - j;
                bool valid = ((unsigned)j < (unsigned)SL) &&
                             (dlt <= WIN) && (dlt >= -WIN);
                lv[r] = valid ? Sr[o] * 0.125f : -1e30f;
                mx = fmaxf(mx, lv[r]);
            }
            #pragma unroll
            for (int off = 16; off; off >>= 1)
                mx = fmaxf(mx, __shfl_xor_sync(0xffffffffu, mx, off));
            float sum = 0.0f;
            #pragma unroll
            for (int r = 0; r < 9; r++) { lv[r] = __expf(lv[r] - mx); sum += lv[r]; }
            #pragma unroll
            for (int off = 16; off; off >>= 1)
                sum += __shfl_xor_sync(0xffffffffu, sum, off);
            float inv = 1.0f / sum;
            __nv_bfloat16* Ph = sP + q * 784;
            __nv_bfloat16* Pl = Ph + 392;
            #pragma unroll
            for (int r = 0; r < 9; r++) {
                float p = lv[r] * inv;
                int o = lane + r * 32;
                __nv_bfloat16 hi = __float2bfloat16_rn(p);
                __nv_bfloat16 lo = __float2bfloat16_rn(p - __bfloat162float(hi));
                Ph[o] = hi;
                Pl[o] = lo;
                wsum[r * 4 + qq] += p;
            }
            #pragma unroll
            for (int r = 9; r < 12; r++) {       // zero pad cols 288..383
                int o = lane + r * 32;
                Ph[o] = __float2bfloat16_rn(0.0f);
                Pl[o] = __float2bfloat16_rn(0.0f);
            }
        }
        __syncthreads();    // publishes softmax P AND the prefetched V chunk 0

        // ---- PV: ctx[32][64] = P[32][384] @ V[384][64] ----
        const int wm = warp >> 2, wn = warp & 3;
        wmma::fragment<wmma::accumulator, 16, 16, 16, float> accv;
        wmma::fill_fragment(accv, 0.0f);

        for (int c2 = 0; c2 < 3; c2++) {
            if (c2 > 0) {       // chunk 0 already resident from prefetch
                int kg = j0 + c2 * 128 + krow;
                bool ok = ((unsigned)kg < (unsigned)SL);
                size_t off = ((size_t)(b * NH + h) * SL + (ok ? kg : 0)) * DH + kdp;
                const uint4 z = make_uint4(0, 0, 0, 0);
                #pragma unroll
                for (int u = 0; u < 4; u++) {
                    *(uint4*)(sKh + krow * 72 + kdp + u * 8) =
                        ok ? *(const uint4*)(g_Vh + off + u * 8) : z;
                    *(uint4*)(sKl + krow * 72 + kdp + u * 8) =
                        ok ? *(const uint4*)(g_Vl + off + u * 8) : z;
                }
                __syncthreads();
            }

            #pragma unroll
            for (int kt = 0; kt < 8; kt++) {
                int k = c2 * 128 + kt * 16;
                wmma::fragment<wmma::matrix_a, 16, 16, 16, __nv_bfloat16,
                               wmma::row_major> phi, plo;
                wmma::load_matrix_sync(phi, sP + wm * 16 * 784 + k, 784);
                wmma::load_matrix_sync(plo, sP + wm * 16 * 784 + 392 + k, 784);
                wmma::fragment<wmma::matrix_b, 16, 16, 16, __nv_bfloat16,
                               wmma::row_major> vhi, vlo;
                wmma::load_matrix_sync(vhi, sKh + kt * 16 * 72 + wn * 16, 72);
                wmma::load_matrix_sync(vlo, sKl + kt * 16 * 72 + wn * 16, 72);
                wmma::mma_sync(accv, phi, vhi, accv);
                wmma::mma_sync(accv, phi, vlo, accv);
                wmma::mma_sync(accv, plo, vhi, accv);
            }
            __syncthreads();    // all warps done reading this V chunk
        }

        wmma::store_matrix_sync(sCtx + wm * 16 * 68 + wn * 16, accv, 68,
                                wmma::mem_row_major);
        __syncthreads();

        {
            int r = tid >> 3, dp = (tid & 7) * 8;
            const float* src = sCtx + r * 68 + dp;
            size_t doff = ((size_t)b * SL + i0 + r) * EMB + h * DH + dp;
            unsigned hv[4], lv2[4];
            #pragma unroll
            for (int u = 0; u < 4; u++) {
                float x = src[u * 2], y = src[u * 2 + 1];
                __nv_bfloat162 hh2 = __floats2bfloat162_rn(x, y);
                float2 hf = __bfloat1622float2(hh2);
                __nv_bfloat162 ll2 = __floats2bfloat162_rn(x - hf.x, y - hf.y);
                hv[u] = *(unsigned*)&hh2;
                lv2[u] = *(unsigned*)&ll2;
            }
            *(uint4*)(g_ctxh + doff) = *(uint4*)hv;
            *(uint4*)(g_ctxl + doff) = *(uint4*)lv2;
        }
    }

    // ---- weights epilogue: head-averaged probs from registers ----
    float* Wb = wout + (size_t)b * SL * SL;
    #pragma unroll
    for (int qq = 0; qq < 4; qq++) {
        int i = i0 + warp * 4 + qq;
        #pragma unroll
        for (int r = 0; r < 9; r++) {
            int o = lane + r * 32;
            int j = j0 + o;
            int dlt = i - j;
            if ((unsigned)j < (unsigned)SL && dlt <= WIN && dlt >= -WIN)
                Wb[(size_t)i * SL + j] = wsum[r * 4 + qq] * 0.125f;
        }
    }
}

// ---------------------------------------------------------------------------
// Kernel 3: output projection (128x256 tiles) + fused max-pool epilogue
// ---------------------------------------------------------------------------
__global__ __launch_bounds__(256, 1)
void out_tc_kernel(const float* __restrict__ bias, float* __restrict__ pooled)
{
    extern __shared__ __align__(16) char smem[];
    const int m0 = blockIdx.y * 128, n0 = blockIdx.x * 256;

    wmma::fragment<wmma::accumulator, 16, 16, 16, float> acc[4][4];
    gemm_wmma_mainloop(g_ctxh, g_ctxl, g_Wouth, g_Woutl, smem, m0, n0, acc);

    float* sC   = (float*)smem;
    float* sRed = (float*)(smem + 128 * SC_LD * 4);     // [2][128]
    const int tid = threadIdx.x;
    const int col = tid & 127;
    const int rh  = tid >> 7;
    const int bb  = m0 >> 11;

    for (int p = 0; p < 2; p++) {
        gemm_store_pass(acc, sC, p);
        __syncthreads();
        float m = -CUDART_INF_F;
        #pragma unroll 8
        for (int r = rh * 64; r < rh * 64 + 64; r++)
            m = fmaxf(m, sC[(size_t)r * SC_LD + col]);
        sRed[rh * 128 + col] = m;
        __syncthreads();
        if (tid < 128) {
            float v = fmaxf(sRed[tid], sRed[128 + tid]) + bias[n0 + p * 128 + tid];
            atomicMaxF(&pooled[bb * EMB + n0 + p * 128 + tid], v);
        }
        __syncthreads();
    }
}

// ---------------------------------------------------------------------------
// Launch
// ---------------------------------------------------------------------------
extern "C" void kernel_launch(void* const* d_in, const int* in_sizes, int n_in,
                              void* d_out, int out_size)
{
    const float *emb = nullptr, *inw = nullptr, *inb = nullptr,
                *ow = nullptr, *ob = nullptr;
    for (int i = 0; i < n_in; i++) {
        switch (in_sizes[i]) {
            case NB * SL * EMB:   emb = (const float*)d_in[i]; break;
            case 3 * EMB * EMB:   inw = (const float*)d_in[i]; break;
            case 3 * EMB:         inb = (const float*)d_in[i]; break;
            case EMB * EMB:       ow  = (const float*)d_in[i]; break;
            case EMB:             ob  = (const float*)d_in[i]; break;
        }
    }

    float* pooled  = (float*)d_out;                 // [4, 512]
    float* weights = pooled + NB * EMB;             // [4, 2048, 2048]

    // 1: one-shot bf16 hi/lo splits (fused)
    split_all_kernel<<<(N4_ALL + 255) / 256, 256>>>(emb, inw, ow);

    // 2: QKV projection (128x256 tiles)
    cudaFuncSetAttribute(qkv_tc_kernel, cudaFuncAttributeMaxDynamicSharedMemorySize,
                         GEMM_SMEM_BYTES);
    qkv_tc_kernel<<<dim3(6, 64), 256, GEMM_SMEM_BYTES>>>(inb);

    // 3: zero the weights band background
    cudaMemsetAsync(weights, 0, (size_t)NB * SL * SL * sizeof(float));

    // 4: attention
    cudaFuncSetAttribute(attn_kernel, cudaFuncAttributeMaxDynamicSharedMemorySize,
                         AT_SMEM_BYTES);
    attn_kernel<<<dim3(SL / 32, NB), 256, AT_SMEM_BYTES>>>(weights);

    // 5: pooled init, 6: output projection + max-pool
    pooled_init_kernel<<<(NB * EMB + 255) / 256, 256>>>(pooled);

    cudaFuncSetAttribute(out_tc_kernel, cudaFuncAttributeMaxDynamicSharedMemorySize,
                         GEMM_SMEM_BYTES);
    out_tc_kernel<<<dim3(2, 64), 256, GEMM_SMEM_BYTES>>>(ob, pooled);
}

// round 15
// speedup vs baseline: 1.0626x; 1.0626x over previous
#include <cuda_runtime.h>
#include <cuda_bf16.h>
#include <math_constants.h>
#include <mma.h>

using namespace nvcuda;

#define NB   4
#define SL   2048
#define EMB  512
#define NH   8
#define DH   64
#define WIN  128

static __device__ __nv_bfloat16 g_Qh[NB * NH * SL * DH];
static __device__ __nv_bfloat16 g_Ql[NB * NH * SL * DH];
static __device__ __nv_bfloat16 g_Kh[NB * NH * SL * DH];
static __device__ __nv_bfloat16 g_Kl[NB * NH * SL * DH];
static __device__ __nv_bfloat16 g_Vh[NB * NH * SL * DH];
static __device__ __nv_bfloat16 g_Vl[NB * NH * SL * DH];

static __device__ __nv_bfloat16 g_Xh[NB * SL * EMB];
static __device__ __nv_bfloat16 g_Xl[NB * SL * EMB];
static __device__ __nv_bfloat16 g_Winh[3 * EMB * EMB];
static __device__ __nv_bfloat16 g_Winl[3 * EMB * EMB];
static __device__ __nv_bfloat16 g_Wouth[EMB * EMB];
static __device__ __nv_bfloat16 g_Woutl[EMB * EMB];
static __device__ __nv_bfloat16 g_ctxh[NB * SL * EMB];
static __device__ __nv_bfloat16 g_ctxl[NB * SL * EMB];

__device__ __forceinline__ unsigned smem_u32(const void* p) {
    unsigned a;
    asm("{ .reg .u64 t; cvta.to.shared.u64 t, %1; cvt.u32.u64 %0, t; }"
        : "=r"(a) : "l"(p));
    return a;
}
#define CP_ASYNC16(dst_u32, src_ptr) \
    asm volatile("cp.async.cg.shared.global [%0], [%1], 16;" \
        :: "r"(dst_u32), "l"(src_ptr))
#define CP_ASYNC16Z(dst_u32, src_ptr, nbytes) \
    asm volatile("cp.async.cg.shared.global [%0], [%1], 16, %2;" \
        :: "r"(dst_u32), "l"(src_ptr), "r"(nbytes))
#define CP_COMMIT() asm volatile("cp.async.commit_group;" ::: "memory")
#define CP_WAIT1()  asm volatile("cp.async.wait_group 1;" ::: "memory")
#define CP_WAIT0()  asm volatile("cp.async.wait_group 0;" ::: "memory")

__device__ __forceinline__ void atomicMaxF(float* addr, float v) {
    if (v >= 0.0f) atomicMax((int*)addr, __float_as_int(v));
    else           atomicMin((unsigned int*)addr, __float_as_uint(v));
}

__global__ void pooled_init_kernel(float* p) {
    int i = blockIdx.x * 256 + threadIdx.x;
    if (i < NB * EMB) p[i] = -CUDART_INF_F;
}

#define N4_X (NB * SL * EMB / 4)
#define N4_W (3 * EMB * EMB / 4)
#define N4_O (EMB * EMB / 4)
#define N4_ALL (N4_X + N4_W + N4_O)

__global__ __launch_bounds__(256)
void split_all_kernel(const float* __restrict__ x,
                      const float* __restrict__ winw,
                      const float* __restrict__ outw)
{
    int i = blockIdx.x * 256 + threadIdx.x;
    if (i >= N4_ALL) return;
    const float* src;
    __nv_bfloat16 *hi, *lo;
    int idx;
    if (i < N4_X)            { src = x;    hi = g_Xh;    lo = g_Xl;    idx = i; }
    else if (i < N4_X + N4_W){ src = winw; hi = g_Winh;  lo = g_Winl;  idx = i - N4_X; }
    else                     { src = outw; hi = g_Wouth; lo = g_Woutl; idx = i - N4_X - N4_W; }

    float4 v = ((const float4*)src)[idx];
    __nv_bfloat162 h01 = __floats2bfloat162_rn(v.x, v.y);
    __nv_bfloat162 h23 = __floats2bfloat162_rn(v.z, v.w);
    float2 f01 = __bfloat1622float2(h01);
    float2 f23 = __bfloat1622float2(h23);
    __nv_bfloat162 l01 = __floats2bfloat162_rn(v.x - f01.x, v.y - f01.y);
    __nv_bfloat162 l23 = __floats2bfloat162_rn(v.z - f23.x, v.w - f23.y);
    uint2 hv, lv;
    hv.x = *(unsigned*)&h01; hv.y = *(unsigned*)&h23;
    lv.x = *(unsigned*)&l01; lv.y = *(unsigned*)&l23;
    ((uint2*)hi)[idx] = hv;
    ((uint2*)lo)[idx] = lv;
}

#define KC    32
#define LDM   40
#define TILEB (128 * LDM * 2)
#define STAGEB (4 * TILEB)
#define SC_LD 132
#define GEMM_SMEM_BYTES (2 * STAGEB)

__device__ __forceinline__ void gemm_wmma(
    const __nv_bfloat16* __restrict__ Ah, const __nv_bfloat16* __restrict__ Al,
    const __nv_bfloat16* __restrict__ Bh, const __nv_bfloat16* __restrict__ Bl,
    char* smem, int m0, int n0)
{
    const int tid = threadIdx.x;
    const int wid = tid >> 5;
    const int wm  = wid >> 2;
    const int wn  = wid & 3;

    wmma::fragment<wmma::accumulator, 16, 16, 16, float> acc[4][2];
    #pragma unroll
    for (int i = 0; i < 4; i++)
        #pragma unroll
        for (int j = 0; j < 2; j++) wmma::fill_fragment(acc[i][j], 0.0f);

    const int row = tid >> 1;
    const int kg  = (tid & 1) * 16;
    const __nv_bfloat16* pAh = Ah + (size_t)(m0 + row) * EMB + kg;
    const __nv_bfloat16* pAl = Al + (size_t)(m0 + row) * EMB + kg;
    const __nv_bfloat16* pBh = Bh + (size_t)(n0 + row) * EMB + kg;
    const __nv_bfloat16* pBl = Bl + (size_t)(n0 + row) * EMB + kg;

    const unsigned sbase = smem_u32(smem);
    const unsigned doff  = (unsigned)((row * LDM + kg) * 2);

    auto issue = [&](int ch, int buf) {
        const int k0 = ch * KC;
        unsigned st = sbase + (unsigned)buf * STAGEB + doff;
        #pragma unroll
        for (int u = 0; u < 2; u++) {
            CP_ASYNC16(st + 0u * TILEB + u * 16, pAh + k0 + u * 8);
            CP_ASYNC16(st + 1u * TILEB + u * 16, pAl + k0 + u * 8);
            CP_ASYNC16(st + 2u * TILEB + u * 16, pBh + k0 + u * 8);
            CP_ASYNC16(st + 3u * TILEB + u * 16, pBl + k0 + u * 8);
        }
        CP_COMMIT();
    };

    issue(0, 0);
    issue(1, 1);

    const int NCH = EMB / KC;
    for (int ch = 0; ch < NCH; ch++) {
        if (ch < NCH - 1) CP_WAIT1(); else CP_WAIT0();
        __syncthreads();

        const char* stage = smem + (size_t)(ch & 1) * STAGEB;
        const __nv_bfloat16* sAhi = (const __nv_bfloat16*)(stage);
        const __nv_bfloat16* sAlo = (const __nv_bfloat16*)(stage + TILEB);
        const __nv_bfloat16* sBhi = (const __nv_bfloat16*)(stage + 2 * TILEB);
        const __nv_bfloat16* sBlo = (const __nv_bfloat16*)(stage + 3 * TILEB);

        #pragma unroll
        for (int ks = 0; ks < KC / 16; ks++) {
            const int kb = ks * 16;
            wmma::fragment<wmma::matrix_a, 16, 16, 16, __nv_bfloat16,
                           wmma::row_major> ahi[4], alo[4];
            wmma::fragment<wmma::matrix_b, 16, 16, 16, __nv_bfloat16,
                           wmma::col_major> bhi[2], blo[2];
            #pragma unroll
            for (int mt = 0; mt < 4; mt++) {
                int r = (wm * 64 + mt * 16) * LDM + kb;
                wmma::load_matrix_sync(ahi[mt], sAhi + r, LDM);
                wmma::load_matrix_sync(alo[mt], sAlo + r, LDM);
            }
            #pragma unroll
            for (int nt = 0; nt < 2; nt++) {
                int r = (wn * 32 + nt * 16) * LDM + kb;
                wmma::load_matrix_sync(bhi[nt], sBhi + r, LDM);
                wmma::load_matrix_sync(blo[nt], sBlo + r, LDM);
            }
            #pragma unroll
            for (int mt = 0; mt < 4; mt++)
                #pragma unroll
                for (int nt = 0; nt < 2; nt++) {
                    wmma::mma_sync(acc[mt][nt], ahi[mt], bhi[nt], acc[mt][nt]);
                    wmma::mma_sync(acc[mt][nt], ahi[mt], blo[nt], acc[mt][nt]);
                    wmma::mma_sync(acc[mt][nt], alo[mt], bhi[nt], acc[mt][nt]);
                }
        }
        __syncthreads();
        if (ch + 2 < NCH) issue(ch + 2, ch & 1);
    }

    float* sC = (float*)smem;
    #pragma unroll
    for (int mt = 0; mt < 4; mt++)
        #pragma unroll
        for (int nt = 0; nt < 2; nt++)
            wmma::store_matrix_sync(
                sC + (size_t)(wm * 64 + mt * 16) * SC_LD + wn * 32 + nt * 16,
                acc[mt][nt], SC_LD, wmma::mem_row_major);
    __syncthreads();
}

__global__ __launch_bounds__(256, 2)
void qkv_tc_kernel(const float* __restrict__ bias)
{
    extern __shared__ __align__(16) char smem[];
    const int m0 = blockIdx.y * 128, n0 = blockIdx.x * 128;
    gemm_wmma(g_Xh, g_Xl, g_Winh, g_Winl, smem, m0, n0);

    const float* sC = (const float*)smem;
    const int tid  = threadIdx.x;
    const int row  = tid >> 1;
    const int koff = (tid & 1) * 32;
    const int m    = m0 + row;
    const int bb   = m >> 11;
    const int s    = m & (SL - 1);

    #pragma unroll
    for (int ph = 0; ph < 2; ph++) {
        const int nb  = n0 + ph * 64;
        const int sel = nb >> 9;
        const int hh  = (nb >> 6) & 7;
        __nv_bfloat16* dh = (sel == 0) ? g_Qh : (sel == 1) ? g_Kh : g_Vh;
        __nv_bfloat16* dl = (sel == 0) ? g_Ql : (sel == 1) ? g_Kl : g_Vl;
        size_t base = (((size_t)(bb * NH + hh) * SL + s) << 6);
        #pragma unroll
        for (int f = 0; f < 8; f++) {
            int c = koff + f * 4;
            float4 v;
            v.x = sC[(size_t)row * SC_LD + ph * 64 + c + 0] + bias[nb + c + 0];
            v.y = sC[(size_t)row * SC_LD + ph * 64 + c + 1] + bias[nb + c + 1];
            v.z = sC[(size_t)row * SC_LD + ph * 64 + c + 2] + bias[nb + c + 2];
            v.w = sC[(size_t)row * SC_LD + ph * 64 + c + 3] + bias[nb + c + 3];
            __nv_bfloat162 h01 = __floats2bfloat162_rn(v.x, v.y);
            __nv_bfloat162 h23 = __floats2bfloat162_rn(v.z, v.w);
            float2 f01 = __bfloat1622float2(h01);
            float2 f23 = __bfloat1622float2(h23);
            __nv_bfloat162 l01 = __floats2bfloat162_rn(v.x - f01.x, v.y - f01.y);
            __nv_bfloat162 l23 = __floats2bfloat162_rn(v.z - f23.x, v.w - f23.y);
            uint2 hv, lv;
            hv.x = *(unsigned*)&h01; hv.y = *(unsigned*)&h23;
            lv.x = *(unsigned*)&l01; lv.y = *(unsigned*)&l23;
            *(uint2*)(dh + base + c) = hv;
            *(uint2*)(dl + base + c) = lv;
        }
    }
}

#define AT_SMEM_BYTES (9216 + 36864 + 50176)

__global__ __launch_bounds__(256, 2)
void attn_kernel(float* __restrict__ wout)
{
    extern __shared__ __align__(16) char smem[];
    __nv_bfloat16* sQh = (__nv_bfloat16*)smem;
    __nv_bfloat16* sQl = sQh + 32 * 72;
    __nv_bfloat16* sKh = (__nv_bfloat16*)(smem + 9216);
    __nv_bfloat16* sKl = sKh + 128 * 72;
    float*         sS  = (float*)(smem + 9216 + 36864);
    __nv_bfloat16* sP  = (__nv_bfloat16*)sS;
    float*         sCtx = (float*)smem;

    const unsigned sb    = smem_u32(smem);
    const unsigned sbK_h = sb + 9216;
    const unsigned sbK_l = sbK_h + 128 * 72 * 2;

    const int tid  = threadIdx.x;
    const int lane = tid & 31;
    const int warp = tid >> 5;
    const int b    = blockIdx.y;
    const int i0   = blockIdx.x * 32;
    const int j0   = i0 - WIN;

    float wsum[36];
    #pragma unroll
    for (int i = 0; i < 36; i++) wsum[i] = 0.0f;

    const int qrow = tid >> 3, qdp = (tid & 7) * 8;
    const int krow = tid >> 1, kdp = (tid & 1) * 32;
    const unsigned kdst_h = sbK_h + (unsigned)(krow * 72 + kdp) * 2;
    const unsigned kdst_l = sbK_l + (unsigned)(krow * 72 + kdp) * 2;

    for (int h = 0; h < NH; h++) {
        const size_t hb = (size_t)(b * NH + h) * SL * DH;
        __syncthreads();

        // issue one K/V chunk fill (zfill when row out of range)
        auto issue_kv = [&](const __nv_bfloat16* Gh, const __nv_bfloat16* Gl,
                            int kbase) {
            int kg = kbase + krow;
            bool ok = ((unsigned)kg < (unsigned)SL);
            int n = ok ? 16 : 0;
            const __nv_bfloat16* ph = Gh + hb + (size_t)(ok ? kg : 0) * DH + kdp;
            const __nv_bfloat16* pl = Gl + hb + (size_t)(ok ? kg : 0) * DH + kdp;
            #pragma unroll
            for (int u = 0; u < 4; u++) {
                CP_ASYNC16Z(kdst_h + u * 16, ph + u * 8, n);
                CP_ASYNC16Z(kdst_l + u * 16, pl + u * 8, n);
            }
            CP_COMMIT();
        };

        // ---- Q tile (always in range) ----
        {
            size_t off = hb + (size_t)(i0 + qrow) * DH + qdp;
            unsigned qd = sb + (unsigned)(qrow * 72 + qdp) * 2;
            CP_ASYNC16(qd,               g_Qh + off);
            CP_ASYNC16(qd + 32 * 72 * 2, g_Ql + off);
            CP_COMMIT();
        }

        // ---- QK scores: 3 chunks of 128 keys ----
        for (int c = 0; c < 3; c++) {
            issue_kv(g_Kh, g_Kl, j0 + c * 128);
            CP_WAIT0();
            __syncthreads();

            wmma::fragment<wmma::accumulator, 16, 16, 16, float> acc[2];
            wmma::fill_fragment(acc[0], 0.0f);
            wmma::fill_fragment(acc[1], 0.0f);
            #pragma unroll
            for (int kt = 0; kt < 4; kt++) {
                wmma::fragment<wmma::matrix_b, 16, 16, 16, __nv_bfloat16,
                               wmma::col_major> bhi, blo;
                wmma::load_matrix_sync(bhi, sKh + warp * 16 * 72 + kt * 16, 72);
                wmma::load_matrix_sync(blo, sKl + warp * 16 * 72 + kt * 16, 72);
                #pragma unroll
                for (int mt = 0; mt < 2; mt++) {
                    wmma::fragment<wmma::matrix_a, 16, 16, 16, __nv_bfloat16,
                                   wmma::row_major> ahi, alo;
                    wmma::load_matrix_sync(ahi, sQh + mt * 16 * 72 + kt * 16, 72);
                    wmma::load_matrix_sync(alo, sQl + mt * 16 * 72 + kt * 16, 72);
                    wmma::mma_sync(acc[mt], ahi, bhi, acc[mt]);
                    wmma::mma_sync(acc[mt], ahi, blo, acc[mt]);
                    wmma::mma_sync(acc[mt], alo, bhi, acc[mt]);
                }
            }
            #pragma unroll
            for (int mt = 0; mt < 2; mt++)
                wmma::store_matrix_sync(sS + mt * 16 * 392 + c * 128 + warp * 16,
                                        acc[mt], 392, wmma::mem_row_major);
            __syncthreads();
        }

        // ---- prefetch V chunk 0 (async, lands during softmax) ----
        issue_kv(g_Vh, g_Vl, j0);

        // ---- softmax + in-place P split ----
        #pragma unroll
        for (int qq = 0; qq < 4; qq++) {
            const int q = warp * 4 + qq;
            const float* Sr = sS + q * 392;
            float lv[9];
            float mx = -1e30f;
            #pragma unroll
            for (int r = 0; r < 9; r++) {
                int o = lane + r * 32;
                int j = j0 + o;
                int dlt = (i0 + q) - j;
                bool valid = ((unsigned)j < (unsigned)SL) &&
                             (dlt <= WIN) && (dlt >= -WIN);
                lv[r] = valid ? Sr[o] * 0.125f : -1e30f;
                mx = fmaxf(mx, lv[r]);
            }
            #pragma unroll
            for (int off = 16; off; off >>= 1)
                mx = fmaxf(mx, __shfl_xor_sync(0xffffffffu, mx, off));
            float sum = 0.0f;
            #pragma unroll
            for (int r = 0; r < 9; r++) { lv[r] = __expf(lv[r] - mx); sum += lv[r]; }
            #pragma unroll
            for (int off = 16; off; off >>= 1)
                sum += __shfl_xor_sync(0xffffffffu, sum, off);
            float inv = 1.0f / sum;
            __nv_bfloat16* Ph = sP + q * 784;
            __nv_bfloat16* Pl = Ph + 392;
            #pragma unroll
            for (int r = 0; r < 9; r++) {
                float p = lv[r] * inv;
                int o = lane + r * 32;
                __nv_bfloat16 hi = __float2bfloat16_rn(p);
                __nv_bfloat16 lo = __float2bfloat16_rn(p - __bfloat162float(hi));
                Ph[o] = hi;
                Pl[o] = lo;
                wsum[r * 4 + qq] += p;
            }
            #pragma unroll
            for (int r = 9; r < 12; r++) {
                int o = lane + r * 32;
                Ph[o] = __float2bfloat16_rn(0.0f);
                Pl[o] = __float2bfloat16_rn(0.0f);
            }
        }
        CP_WAIT0();
        __syncthreads();

        // ---- PV ----
        const int wm = warp >> 2, wn = warp & 3;
        wmma::fragment<wmma::accumulator, 16, 16, 16, float> accv;
        wmma::fill_fragment(accv, 0.0f);

        for (int c2 = 0; c2 < 3; c2++) {
            if (c2 > 0) {
                issue_kv(g_Vh, g_Vl, j0 + c2 * 128);
                CP_WAIT0();
                __syncthreads();
            }

            #pragma unroll
            for (int kt = 0; kt < 8; kt++) {
                int k = c2 * 128 + kt * 16;
                wmma::fragment<wmma::matrix_a, 16, 16, 16, __nv_bfloat16,
                               wmma::row_major> phi, plo;
                wmma::load_matrix_sync(phi, sP + wm * 16 * 784 + k, 784);
                wmma::load_matrix_sync(plo, sP + wm * 16 * 784 + 392 + k, 784);
                wmma::fragment<wmma::matrix_b, 16, 16, 16, __nv_bfloat16,
                               wmma::row_major> vhi, vlo;
                wmma::load_matrix_sync(vhi, sKh + kt * 16 * 72 + wn * 16, 72);
                wmma::load_matrix_sync(vlo, sKl + kt * 16 * 72 + wn * 16, 72);
                wmma::mma_sync(accv, phi, vhi, accv);
                wmma::mma_sync(accv, phi, vlo, accv);
                wmma::mma_sync(accv, plo, vhi, accv);
            }
            __syncthreads();
        }

        wmma::store_matrix_sync(sCtx + wm * 16 * 68 + wn * 16, accv, 68,
                                wmma::mem_row_major);
        __syncthreads();

        {
            int r = tid >> 3, dp = (tid & 7) * 8;
            const float* src = sCtx + r * 68 + dp;
            size_t doff = ((size_t)b * SL + i0 + r) * EMB + h * DH + dp;
            unsigned hv[4], lv2[4];
            #pragma unroll
            for (int u = 0; u < 4; u++) {
                float x = src[u * 2], y = src[u * 2 + 1];
                __nv_bfloat162 hh2 = __floats2bfloat162_rn(x, y);
                float2 hf = __bfloat1622float2(hh2);
                __nv_bfloat162 ll2 = __floats2bfloat162_rn(x - hf.x, y - hf.y);
                hv[u] = *(unsigned*)&hh2;
                lv2[u] = *(unsigned*)&ll2;
            }
            *(uint4*)(g_ctxh + doff) = *(uint4*)hv;
            *(uint4*)(g_ctxl + doff) = *(uint4*)lv2;
        }
    }

    float* Wb = wout + (size_t)b * SL * SL;
    #pragma unroll
    for (int qq = 0; qq < 4; qq++) {
        int i = i0 + warp * 4 + qq;
        #pragma unroll
        for (int r = 0; r < 9; r++) {
            int o = lane + r * 32;
            int j = j0 + o;
            int dlt = i - j;
            if ((unsigned)j < (unsigned)SL && dlt <= WIN && dlt >= -WIN)
                Wb[(size_t)i * SL + j] = wsum[r * 4 + qq] * 0.125f;
        }
    }
}

__global__ __launch_bounds__(256, 2)
void out_tc_kernel(const float* __restrict__ bias, float* __restrict__ pooled)
{
    extern __shared__ __align__(16) char smem[];
    const int m0 = blockIdx.y * 128, n0 = blockIdx.x * 128;
    gemm_wmma(g_ctxh, g_ctxl, g_Wouth, g_Woutl, smem, m0, n0);

    const float* sC   = (const float*)smem;
    float*       sRed = (float*)(smem + 128 * SC_LD * 4);
    const int tid = threadIdx.x;
    const int col = tid & 127;
    const int rh  = tid >> 7;

    float m = -CUDART_INF_F;
    #pragma unroll 8
    for (int r = rh * 64; r < rh * 64 + 64; r++)
        m = fmaxf(m, sC[(size_t)r * SC_LD + col]);
    sRed[rh * 128 + col] = m;
    __syncthreads();
    if (tid < 128) {
        float v = fmaxf(sRed[tid], sRed[128 + tid]) + bias[n0 + tid];
        int bb = m0 >> 11;
        atomicMaxF(&pooled[bb * EMB + n0 + tid], v);
    }
}

extern "C" void kernel_launch(void* const* d_in, const int* in_sizes, int n_in,
                              void* d_out, int out_size)
{
    const float *emb = nullptr, *inw = nullptr, *inb = nullptr,
                *ow = nullptr, *ob = nullptr;
    for (int i = 0; i < n_in; i++) {
        switch (in_sizes[i]) {
            case NB * SL * EMB:   emb = (const float*)d_in[i]; break;
            case 3 * EMB * EMB:   inw = (const float*)d_in[i]; break;
            case 3 * EMB:         inb = (const float*)d_in[i]; break;
            case EMB * EMB:       ow  = (const float*)d_in[i]; break;
            case EMB:             ob  = (const float*)d_in[i]; break;
        }
    }

    float* pooled  = (float*)d_out;
    float* weights = pooled + NB * EMB;

    split_all_kernel<<<(N4_ALL + 255) / 256, 256>>>(emb, inw, ow);

    cudaFuncSetAttribute(qkv_tc_kernel, cudaFuncAttributeMaxDynamicSharedMemorySize,
                         GEMM_SMEM_BYTES);
    qkv_tc_kernel<<<dim3(12, 64), 256, GEMM_SMEM_BYTES>>>(inb);

    cudaMemsetAsync(weights, 0, (size_t)NB * SL * SL * sizeof(float));

    cudaFuncSetAttribute(attn_kernel, cudaFuncAttributeMaxDynamicSharedMemorySize,
                         AT_SMEM_BYTES);
    attn_kernel<<<dim3(SL / 32, NB), 256, AT_SMEM_BYTES>>>(weights);

    pooled_init_kernel<<<(NB * EMB + 255) / 256, 256>>>(pooled);

    cudaFuncSetAttribute(out_tc_kernel, cudaFuncAttributeMaxDynamicSharedMemorySize,
                         GEMM_SMEM_BYTES);
    out_tc_kernel<<<dim3(4, 64), 256, GEMM_SMEM_BYTES>>>(ob, pooled);
}

// round 17
// speedup vs baseline: 1.1259x; 1.0596x over previous
#include <cuda_runtime.h>
#include <cuda_bf16.h>
#include <math_constants.h>
#include <mma.h>

using namespace nvcuda;

#define NB   4
#define SL   2048
#define EMB  512
#define NH   8
#define DH   64
#define WIN  128

static __device__ __nv_bfloat16 g_Qh[NB * NH * SL * DH];
static __device__ __nv_bfloat16 g_Ql[NB * NH * SL * DH];
static __device__ __nv_bfloat16 g_Kh[NB * NH * SL * DH];
static __device__ __nv_bfloat16 g_Kl[NB * NH * SL * DH];
static __device__ __nv_bfloat16 g_Vh[NB * NH * SL * DH];
static __device__ __nv_bfloat16 g_Vl[NB * NH * SL * DH];

static __device__ __nv_bfloat16 g_Xh[NB * SL * EMB];
static __device__ __nv_bfloat16 g_Xl[NB * SL * EMB];
static __device__ __nv_bfloat16 g_Winh[3 * EMB * EMB];
static __device__ __nv_bfloat16 g_Winl[3 * EMB * EMB];
static __device__ __nv_bfloat16 g_Wouth[EMB * EMB];
static __device__ __nv_bfloat16 g_Woutl[EMB * EMB];
static __device__ __nv_bfloat16 g_ctxh[NB * SL * EMB];
static __device__ __nv_bfloat16 g_ctxl[NB * SL * EMB];

__device__ __forceinline__ unsigned smem_u32(const void* p) {
    unsigned a;
    asm("{ .reg .u64 t; cvta.to.shared.u64 t, %1; cvt.u32.u64 %0, t; }"
        : "=r"(a) : "l"(p));
    return a;
}
#define CP_ASYNC16(dst_u32, src_ptr) \
    asm volatile("cp.async.cg.shared.global [%0], [%1], 16;" \
        :: "r"(dst_u32), "l"(src_ptr))
#define CP_ASYNC16Z(dst_u32, src_ptr, nbytes) \
    asm volatile("cp.async.cg.shared.global [%0], [%1], 16, %2;" \
        :: "r"(dst_u32), "l"(src_ptr), "r"(nbytes))
#define CP_COMMIT() asm volatile("cp.async.commit_group;" ::: "memory")
#define CP_WAIT1()  asm volatile("cp.async.wait_group 1;" ::: "memory")
#define CP_WAIT0()  asm volatile("cp.async.wait_group 0;" ::: "memory")

__device__ __forceinline__ void atomicMaxF(float* addr, float v) {
    if (v >= 0.0f) atomicMax((int*)addr, __float_as_int(v));
    else           atomicMin((unsigned int*)addr, __float_as_uint(v));
}

__global__ void pooled_init_kernel(float* p) {
    int i = blockIdx.x * 256 + threadIdx.x;
    if (i < NB * EMB) p[i] = -CUDART_INF_F;
}

#define N4_X (NB * SL * EMB / 4)
#define N4_W (3 * EMB * EMB / 4)
#define N4_O (EMB * EMB / 4)
#define N4_ALL (N4_X + N4_W + N4_O)

__global__ __launch_bounds__(256)
void split_all_kernel(const float* __restrict__ x,
                      const float* __restrict__ winw,
                      const float* __restrict__ outw)
{
    int i = blockIdx.x * 256 + threadIdx.x;
    if (i >= N4_ALL) return;
    const float* src;
    __nv_bfloat16 *hi, *lo;
    int idx;
    if (i < N4_X)            { src = x;    hi = g_Xh;    lo = g_Xl;    idx = i; }
    else if (i < N4_X + N4_W){ src = winw; hi = g_Winh;  lo = g_Winl;  idx = i - N4_X; }
    else                     { src = outw; hi = g_Wouth; lo = g_Woutl; idx = i - N4_X - N4_W; }

    float4 v = ((const float4*)src)[idx];
    __nv_bfloat162 h01 = __floats2bfloat162_rn(v.x, v.y);
    __nv_bfloat162 h23 = __floats2bfloat162_rn(v.z, v.w);
    float2 f01 = __bfloat1622float2(h01);
    float2 f23 = __bfloat1622float2(h23);
    __nv_bfloat162 l01 = __floats2bfloat162_rn(v.x - f01.x, v.y - f01.y);
    __nv_bfloat162 l23 = __floats2bfloat162_rn(v.z - f23.x, v.w - f23.y);
    uint2 hv, lv;
    hv.x = *(unsigned*)&h01; hv.y = *(unsigned*)&h23;
    lv.x = *(unsigned*)&l01; lv.y = *(unsigned*)&l23;
    ((uint2*)hi)[idx] = hv;
    ((uint2*)lo)[idx] = lv;
}

#define KC    32
#define LDM   40
#define TILEB (128 * LDM * 2)
#define STAGEB (4 * TILEB)
#define SC_LD 132
#define GEMM_SMEM_BYTES (2 * STAGEB)

__device__ __forceinline__ void gemm_wmma(
    const __nv_bfloat16* __restrict__ Ah, const __nv_bfloat16* __restrict__ Al,
    const __nv_bfloat16* __restrict__ Bh, const __nv_bfloat16* __restrict__ Bl,
    char* smem, int m0, int n0)
{
    const int tid = threadIdx.x;
    const int wid = tid >> 5;
    const int wm  = wid >> 2;
    const int wn  = wid & 3;

    wmma::fragment<wmma::accumulator, 16, 16, 16, float> acc[4][2];
    #pragma unroll
    for (int i = 0; i < 4; i++)
        #pragma unroll
        for (int j = 0; j < 2; j++) wmma::fill_fragment(acc[i][j], 0.0f);

    const int row = tid >> 1;
    const int kg  = (tid & 1) * 16;
    const __nv_bfloat16* pAh = Ah + (size_t)(m0 + row) * EMB + kg;
    const __nv_bfloat16* pAl = Al + (size_t)(m0 + row) * EMB + kg;
    const __nv_bfloat16* pBh = Bh + (size_t)(n0 + row) * EMB + kg;
    const __nv_bfloat16* pBl = Bl + (size_t)(n0 + row) * EMB + kg;

    const unsigned sbase = smem_u32(smem);
    const unsigned doff  = (unsigned)((row * LDM + kg) * 2);

    auto issue = [&](int ch, int buf) {
        const int k0 = ch * KC;
        unsigned st = sbase + (unsigned)buf * STAGEB + doff;
        #pragma unroll
        for (int u = 0; u < 2; u++) {
            CP_ASYNC16(st + 0u * TILEB + u * 16, pAh + k0 + u * 8);
            CP_ASYNC16(st + 1u * TILEB + u * 16, pAl + k0 + u * 8);
            CP_ASYNC16(st + 2u * TILEB + u * 16, pBh + k0 + u * 8);
            CP_ASYNC16(st + 3u * TILEB + u * 16, pBl + k0 + u * 8);
        }
        CP_COMMIT();
    };

    issue(0, 0);
    issue(1, 1);

    const int NCH = EMB / KC;
    for (int ch = 0; ch < NCH; ch++) {
        if (ch < NCH - 1) CP_WAIT1(); else CP_WAIT0();
        __syncthreads();

        const char* stage = smem + (size_t)(ch & 1) * STAGEB;
        const __nv_bfloat16* sAhi = (const __nv_bfloat16*)(stage);
        const __nv_bfloat16* sAlo = (const __nv_bfloat16*)(stage + TILEB);
        const __nv_bfloat16* sBhi = (const __nv_bfloat16*)(stage + 2 * TILEB);
        const __nv_bfloat16* sBlo = (const __nv_bfloat16*)(stage + 3 * TILEB);

        #pragma unroll
        for (int ks = 0; ks < KC / 16; ks++) {
            const int kb = ks * 16;
            wmma::fragment<wmma::matrix_a, 16, 16, 16, __nv_bfloat16,
                           wmma::row_major> ahi[4], alo[4];
            wmma::fragment<wmma::matrix_b, 16, 16, 16, __nv_bfloat16,
                           wmma::col_major> bhi[2], blo[2];
            #pragma unroll
            for (int mt = 0; mt < 4; mt++) {
                int r = (wm * 64 + mt * 16) * LDM + kb;
                wmma::load_matrix_sync(ahi[mt], sAhi + r, LDM);
                wmma::load_matrix_sync(alo[mt], sAlo + r, LDM);
            }
            #pragma unroll
            for (int nt = 0; nt < 2; nt++) {
                int r = (wn * 32 + nt * 16) * LDM + kb;
                wmma::load_matrix_sync(bhi[nt], sBhi + r, LDM);
                wmma::load_matrix_sync(blo[nt], sBlo + r, LDM);
            }
            #pragma unroll
            for (int mt = 0; mt < 4; mt++)
                #pragma unroll
                for (int nt = 0; nt < 2; nt++) {
                    wmma::mma_sync(acc[mt][nt], ahi[mt], bhi[nt], acc[mt][nt]);
                    wmma::mma_sync(acc[mt][nt], ahi[mt], blo[nt], acc[mt][nt]);
                    wmma::mma_sync(acc[mt][nt], alo[mt], bhi[nt], acc[mt][nt]);
                }
        }
        __syncthreads();
        if (ch + 2 < NCH) issue(ch + 2, ch & 1);
    }

    float* sC = (float*)smem;
    #pragma unroll
    for (int mt = 0; mt < 4; mt++)
        #pragma unroll
        for (int nt = 0; nt < 2; nt++)
            wmma::store_matrix_sync(
                sC + (size_t)(wm * 64 + mt * 16) * SC_LD + wn * 32 + nt * 16,
                acc[mt][nt], SC_LD, wmma::mem_row_major);
    __syncthreads();
}

__global__ __launch_bounds__(256, 2)
void qkv_tc_kernel(const float* __restrict__ bias)
{
    extern __shared__ __align__(16) char smem[];
    const int m0 = blockIdx.y * 128, n0 = blockIdx.x * 128;
    gemm_wmma(g_Xh, g_Xl, g_Winh, g_Winl, smem, m0, n0);

    const float* sC = (const float*)smem;
    const int tid  = threadIdx.x;
    const int row  = tid >> 1;
    const int koff = (tid & 1) * 32;
    const int m    = m0 + row;
    const int bb   = m >> 11;
    const int s    = m & (SL - 1);

    #pragma unroll
    for (int ph = 0; ph < 2; ph++) {
        const int nb  = n0 + ph * 64;
        const int sel = nb >> 9;
        const int hh  = (nb >> 6) & 7;
        __nv_bfloat16* dh = (sel == 0) ? g_Qh : (sel == 1) ? g_Kh : g_Vh;
        __nv_bfloat16* dl = (sel == 0) ? g_Ql : (sel == 1) ? g_Kl : g_Vl;
        size_t base = (((size_t)(bb * NH + hh) * SL + s) << 6);
        #pragma unroll
        for (int f = 0; f < 8; f++) {
            int c = koff + f * 4;
            float4 v;
            v.x = sC[(size_t)row * SC_LD + ph * 64 + c + 0] + bias[nb + c + 0];
            v.y = sC[(size_t)row * SC_LD + ph * 64 + c + 1] + bias[nb + c + 1];
            v.z = sC[(size_t)row * SC_LD + ph * 64 + c + 2] + bias[nb + c + 2];
            v.w = sC[(size_t)row * SC_LD + ph * 64 + c + 3] + bias[nb + c + 3];
            __nv_bfloat162 h01 = __floats2bfloat162_rn(v.x, v.y);
            __nv_bfloat162 h23 = __floats2bfloat162_rn(v.z, v.w);
            float2 f01 = __bfloat1622float2(h01);
            float2 f23 = __bfloat1622float2(h23);
            __nv_bfloat162 l01 = __floats2bfloat162_rn(v.x - f01.x, v.y - f01.y);
            __nv_bfloat162 l23 = __floats2bfloat162_rn(v.z - f23.x, v.w - f23.y);
            uint2 hv, lv;
            hv.x = *(unsigned*)&h01; hv.y = *(unsigned*)&h23;
            lv.x = *(unsigned*)&l01; lv.y = *(unsigned*)&l23;
            *(uint2*)(dh + base + c) = hv;
            *(uint2*)(dl + base + c) = lv;
        }
    }
}

// ---------------------------------------------------------------------------
// Banded attention: one block per (qtile, batch, head). Grid (64,4,8)=2048
// fine-grained blocks -> full 296-slot occupancy and load balance.
// Head-average accumulated via atomicAdd into pre-zeroed weights band.
// ---------------------------------------------------------------------------
#define AT_SMEM_BYTES (9216 + 36864 + 50176)

__global__ __launch_bounds__(256, 2)
void attn_kernel(float* __restrict__ wout)
{
    extern __shared__ __align__(16) char smem[];
    __nv_bfloat16* sQh = (__nv_bfloat16*)smem;
    __nv_bfloat16* sQl = sQh + 32 * 72;
    __nv_bfloat16* sKh = (__nv_bfloat16*)(smem + 9216);
    __nv_bfloat16* sKl = sKh + 128 * 72;
    float*         sS  = (float*)(smem + 9216 + 36864);
    __nv_bfloat16* sP  = (__nv_bfloat16*)sS;
    float*         sCtx = (float*)smem;

    const unsigned sb    = smem_u32(smem);
    const unsigned sbK_h = sb + 9216;
    const unsigned sbK_l = sbK_h + 128 * 72 * 2;

    const int tid  = threadIdx.x;
    const int lane = tid & 31;
    const int warp = tid >> 5;
    const int b    = blockIdx.y;
    const int h    = blockIdx.z;
    const int i0   = blockIdx.x * 32;
    const int j0   = i0 - WIN;

    float wsum[36];
    #pragma unroll
    for (int i = 0; i < 36; i++) wsum[i] = 0.0f;

    const int qrow = tid >> 3, qdp = (tid & 7) * 8;
    const int krow = tid >> 1, kdp = (tid & 1) * 32;
    const unsigned kdst_h = sbK_h + (unsigned)(krow * 72 + kdp) * 2;
    const unsigned kdst_l = sbK_l + (unsigned)(krow * 72 + kdp) * 2;
    const size_t hb = (size_t)(b * NH + h) * SL * DH;

    auto issue_kv = [&](const __nv_bfloat16* Gh, const __nv_bfloat16* Gl,
                        int kbase) {
        int kg = kbase + krow;
        bool ok = ((unsigned)kg < (unsigned)SL);
        int n = ok ? 16 : 0;
        const __nv_bfloat16* ph = Gh + hb + (size_t)(ok ? kg : 0) * DH + kdp;
        const __nv_bfloat16* pl = Gl + hb + (size_t)(ok ? kg : 0) * DH + kdp;
        #pragma unroll
        for (int u = 0; u < 4; u++) {
            CP_ASYNC16Z(kdst_h + u * 16, ph + u * 8, n);
            CP_ASYNC16Z(kdst_l + u * 16, pl + u * 8, n);
        }
        CP_COMMIT();
    };

    // ---- Q tile (always in range) ----
    {
        size_t off = hb + (size_t)(i0 + qrow) * DH + qdp;
        unsigned qd = sb + (unsigned)(qrow * 72 + qdp) * 2;
        CP_ASYNC16(qd,               g_Qh + off);
        CP_ASYNC16(qd + 32 * 72 * 2, g_Ql + off);
        CP_COMMIT();
    }

    // ---- QK scores: 3 chunks of 128 keys ----
    for (int c = 0; c < 3; c++) {
        issue_kv(g_Kh, g_Kl, j0 + c * 128);
        CP_WAIT0();
        __syncthreads();

        wmma::fragment<wmma::accumulator, 16, 16, 16, float> acc[2];
        wmma::fill_fragment(acc[0], 0.0f);
        wmma::fill_fragment(acc[1], 0.0f);
        #pragma unroll
        for (int kt = 0; kt < 4; kt++) {
            wmma::fragment<wmma::matrix_b, 16, 16, 16, __nv_bfloat16,
                           wmma::col_major> bhi, blo;
            wmma::load_matrix_sync(bhi, sKh + warp * 16 * 72 + kt * 16, 72);
            wmma::load_matrix_sync(blo, sKl + warp * 16 * 72 + kt * 16, 72);
            #pragma unroll
            for (int mt = 0; mt < 2; mt++) {
                wmma::fragment<wmma::matrix_a, 16, 16, 16, __nv_bfloat16,
                               wmma::row_major> ahi, alo;
                wmma::load_matrix_sync(ahi, sQh + mt * 16 * 72 + kt * 16, 72);
                wmma::load_matrix_sync(alo, sQl + mt * 16 * 72 + kt * 16, 72);
                wmma::mma_sync(acc[mt], ahi, bhi, acc[mt]);
                wmma::mma_sync(acc[mt], ahi, blo, acc[mt]);
                wmma::mma_sync(acc[mt], alo, bhi, acc[mt]);
            }
        }
        #pragma unroll
        for (int mt = 0; mt < 2; mt++)
            wmma::store_matrix_sync(sS + mt * 16 * 392 + c * 128 + warp * 16,
                                    acc[mt], 392, wmma::mem_row_major);
        __syncthreads();
    }

    // ---- prefetch V chunk 0 (async, lands during softmax) ----
    issue_kv(g_Vh, g_Vl, j0);

    // ---- softmax + in-place P split (warp owns rows warp*4..+3) ----
    #pragma unroll
    for (int qq = 0; qq < 4; qq++) {
        const int q = warp * 4 + qq;
        const float* Sr = sS + q * 392;
        float lv[9];
        float mx = -1e30f;
        #pragma unroll
        for (int r = 0; r < 9; r++) {
            int o = lane + r * 32;
            int j = j0 + o;
            int dlt = (i0 + q) - j;
            bool valid = ((unsigned)j < (unsigned)SL) &&
                         (dlt <= WIN) && (dlt >= -WIN);
            lv[r] = valid ? Sr[o] * 0.125f : -1e30f;
            mx = fmaxf(mx, lv[r]);
        }
        #pragma unroll
        for (int off = 16; off; off >>= 1)
            mx = fmaxf(mx, __shfl_xor_sync(0xffffffffu, mx, off));
        float sum = 0.0f;
        #pragma unroll
        for (int r = 0; r < 9; r++) { lv[r] = __expf(lv[r] - mx); sum += lv[r]; }
        #pragma unroll
        for (int off = 16; off; off >>= 1)
            sum += __shfl_xor_sync(0xffffffffu, sum, off);
        float inv = 1.0f / sum;
        __nv_bfloat16* Ph = sP + q * 784;
        __nv_bfloat16* Pl = Ph + 392;
        #pragma unroll
        for (int r = 0; r < 9; r++) {
            float p = lv[r] * inv;
            int o = lane + r * 32;
            __nv_bfloat16 hi = __float2bfloat16_rn(p);
            __nv_bfloat16 lo = __float2bfloat16_rn(p - __bfloat162float(hi));
            Ph[o] = hi;
            Pl[o] = lo;
            wsum[r * 4 + qq] += p;
        }
        #pragma unroll
        for (int r = 9; r < 12; r++) {
            int o = lane + r * 32;
            Ph[o] = __float2bfloat16_rn(0.0f);
            Pl[o] = __float2bfloat16_rn(0.0f);
        }
    }
    CP_WAIT0();
    __syncthreads();

    // ---- PV: ctx[32][64] = P[32][384] @ V[384][64] ----
    const int wm = warp >> 2, wn = warp & 3;
    wmma::fragment<wmma::accumulator, 16, 16, 16, float> accv;
    wmma::fill_fragment(accv, 0.0f);

    for (int c2 = 0; c2 < 3; c2++) {
        if (c2 > 0) {
            issue_kv(g_Vh, g_Vl, j0 + c2 * 128);
            CP_WAIT0();
            __syncthreads();
        }

        #pragma unroll
        for (int kt = 0; kt < 8; kt++) {
            int k = c2 * 128 + kt * 16;
            wmma::fragment<wmma::matrix_a, 16, 16, 16, __nv_bfloat16,
                           wmma::row_major> phi, plo;
            wmma::load_matrix_sync(phi, sP + wm * 16 * 784 + k, 784);
            wmma::load_matrix_sync(plo, sP + wm * 16 * 784 + 392 + k, 784);
            wmma::fragment<wmma::matrix_b, 16, 16, 16, __nv_bfloat16,
                           wmma::row_major> vhi, vlo;
            wmma::load_matrix_sync(vhi, sKh + kt * 16 * 72 + wn * 16, 72);
            wmma::load_matrix_sync(vlo, sKl + kt * 16 * 72 + wn * 16, 72);
            wmma::mma_sync(accv, phi, vhi, accv);
            wmma::mma_sync(accv, phi, vlo, accv);
            wmma::mma_sync(accv, plo, vhi, accv);
        }
        __syncthreads();
    }

    wmma::store_matrix_sync(sCtx + wm * 16 * 68 + wn * 16, accv, 68,
                            wmma::mem_row_major);
    __syncthreads();

    // ---- ctx slice (disjoint per head) ----
    {
        int r = tid >> 3, dp = (tid & 7) * 8;
        const float* src = sCtx + r * 68 + dp;
        size_t doff = ((size_t)b * SL + i0 + r) * EMB + h * DH + dp;
        unsigned hv[4], lv2[4];
        #pragma unroll
        for (int u = 0; u < 4; u++) {
            float x = src[u * 2], y = src[u * 2 + 1];
            __nv_bfloat162 hh2 = __floats2bfloat162_rn(x, y);
            float2 hf = __bfloat1622float2(hh2);
            __nv_bfloat162 ll2 = __floats2bfloat162_rn(x - hf.x, y - hf.y);
            hv[u] = *(unsigned*)&hh2;
            lv2[u] = *(unsigned*)&ll2;
        }
        *(uint4*)(g_ctxh + doff) = *(uint4*)hv;
        *(uint4*)(g_ctxl + doff) = *(uint4*)lv2;
    }

    // ---- weights: accumulate this head's probs into the band ----
    float* Wb = wout + (size_t)b * SL * SL;
    #pragma unroll
    for (int qq = 0; qq < 4; qq++) {
        int i = i0 + warp * 4 + qq;
        #pragma unroll
        for (int r = 0; r < 9; r++) {
            int o = lane + r * 32;
            int j = j0 + o;
            int dlt = i - j;
            if ((unsigned)j < (unsigned)SL && dlt <= WIN && dlt >= -WIN)
                atomicAdd(&Wb[(size_t)i * SL + j], wsum[r * 4 + qq] * 0.125f);
        }
    }
}

__global__ __launch_bounds__(256, 2)
void out_tc_kernel(const float* __restrict__ bias, float* __restrict__ pooled)
{
    extern __shared__ __align__(16) char smem[];
    const int m0 = blockIdx.y * 128, n0 = blockIdx.x * 128;
    gemm_wmma(g_ctxh, g_ctxl, g_Wouth, g_Woutl, smem, m0, n0);

    const float* sC   = (const float*)smem;
    float*       sRed = (float*)(smem + 128 * SC_LD * 4);
    const int tid = threadIdx.x;
    const int col = tid & 127;
    const int rh  = tid >> 7;

    float m = -CUDART_INF_F;
    #pragma unroll 8
    for (int r = rh * 64; r < rh * 64 + 64; r++)
        m = fmaxf(m, sC[(size_t)r * SC_LD + col]);
    sRed[rh * 128 + col] = m;
    __syncthreads();
    if (tid < 128) {
        float v = fmaxf(sRed[tid], sRed[128 + tid]) + bias[n0 + tid];
        int bb = m0 >> 11;
        atomicMaxF(&pooled[bb * EMB + n0 + tid], v);
    }
}

extern "C" void kernel_launch(void* const* d_in, const int* in_sizes, int n_in,
                              void* d_out, int out_size)
{
    const float *emb = nullptr, *inw = nullptr, *inb = nullptr,
                *ow = nullptr, *ob = nullptr;
    for (int i = 0; i < n_in; i++) {
        switch (in_sizes[i]) {
            case NB * SL * EMB:   emb = (const float*)d_in[i]; break;
            case 3 * EMB * EMB:   inw = (const float*)d_in[i]; break;
            case 3 * EMB:         inb = (const float*)d_in[i]; break;
            case EMB * EMB:       ow  = (const float*)d_in[i]; break;
            case EMB:             ob  = (const float*)d_in[i]; break;
        }
    }

    float* pooled  = (float*)d_out;
    float* weights = pooled + NB * EMB;

    // 1: splits  2: qkv  3: memset  4: pooled_init  5: attn (ncu slot)  6: out
    split_all_kernel<<<(N4_ALL + 255) / 256, 256>>>(emb, inw, ow);

    cudaFuncSetAttribute(qkv_tc_kernel, cudaFuncAttributeMaxDynamicSharedMemorySize,
                         GEMM_SMEM_BYTES);
    qkv_tc_kernel<<<dim3(12, 64), 256, GEMM_SMEM_BYTES>>>(inb);

    cudaMemsetAsync(weights, 0, (size_t)NB * SL * SL * sizeof(float));

    pooled_init_kernel<<<(NB * EMB + 255) / 256, 256>>>(pooled);

    cudaFuncSetAttribute(attn_kernel, cudaFuncAttributeMaxDynamicSharedMemorySize,
                         AT_SMEM_BYTES);
    attn_kernel<<<dim3(SL / 32, NB, NH), 256, AT_SMEM_BYTES>>>(weights);

    cudaFuncSetAttribute(out_tc_kernel, cudaFuncAttributeMaxDynamicSharedMemorySize,
                         GEMM_SMEM_BYTES);
    out_tc_kernel<<<dim3(4, 64), 256, GEMM_SMEM_BYTES>>>(ob, pooled);
}